// round 3
// baseline (speedup 1.0000x reference)
#include <cuda_runtime.h>
#include <cuda_bf16.h>
#include <math.h>

#define N_NODES 32768
#define HID     256
#define NE      524288
#define NH      8
#define HC      32
#define NG      64
#define NPG     512
#define E2      (NE + N_NODES)   /* 557056 edges incl. self loops */

/* ------------------------------------------------------------------ */
/* scratch (device globals; no runtime allocation allowed)            */
/* ------------------------------------------------------------------ */
__device__ __align__(128) float    g_xl   [N_NODES * HID];
__device__ __align__(128) float    g_xr   [N_NODES * HID];
__device__ __align__(128) float    g_gat  [N_NODES * HID];
__device__ __align__(128) float    g_local[N_NODES * HID];
__device__ __align__(128) float    g_attn [N_NODES * HID];
__device__ __align__(128) float    g_glob [N_NODES * HID];
__device__ __align__(128) float    g_comb [N_NODES * HID];
__device__ __align__(128) float    g_qkv  [N_NODES * 3 * HID];
__device__ __align__(128) float    g_mid  [N_NODES * 4 * HID];
__device__ __align__(128) float    g_score[E2 * NH];          /* scores, then exp */
__device__ __align__(128) unsigned g_smax [N_NODES * NH];
__device__ __align__(128) float    g_ssum [N_NODES * NH];
__device__ __align__(128) float    g_deg  [N_NODES];
__device__ __align__(128) float    g_ea   [N_NODES * 2];      /* sum -> mean */

/* ------------------------------------------------------------------ */
/* helpers                                                            */
/* ------------------------------------------------------------------ */
__device__ __forceinline__ unsigned fenc(float f) {
    unsigned u = __float_as_uint(f);
    return (u & 0x80000000u) ? ~u : (u | 0x80000000u);
}
__device__ __forceinline__ float fdec(unsigned u) {
    return (u & 0x80000000u) ? __uint_as_float(u & 0x7fffffffu)
                             : __uint_as_float(~u);
}
__device__ __forceinline__ float warp_sum(float v) {
    #pragma unroll
    for (int o = 16; o; o >>= 1) v += __shfl_xor_sync(0xffffffffu, v, o);
    return v;
}
__device__ __forceinline__ void red_add_v4(float* p, float a, float b, float c, float d) {
    asm volatile("red.global.add.v4.f32 [%0], {%1,%2,%3,%4};"
                 :: "l"(p), "f"(a), "f"(b), "f"(c), "f"(d) : "memory");
}

/* ------------------------------------------------------------------ */
/* init: zero all accumulators                                        */
/* ------------------------------------------------------------------ */
__global__ void k_init() {
    int i = blockIdx.x * 256 + threadIdx.x;          /* grid covers N*HID */
    g_gat[i] = 0.f;
    if (i < N_NODES)       g_deg[i]  = 0.f;
    if (i < N_NODES * 2)   g_ea[i]   = 0.f;
    if (i < N_NODES * NH) { g_smax[i] = 0u; g_ssum[i] = 0.f; }
}

/* degree + edge-attr sums over incoming edges */
__global__ void k_deg(const int* __restrict__ ei, const float* __restrict__ ea) {
    int e = blockIdx.x * 256 + threadIdx.x;
    if (e >= NE) return;
    int dst = ei[NE + e];
    atomicAdd(&g_deg[dst], 1.f);
    atomicAdd(&g_ea[2 * dst],     ea[2 * e]);
    atomicAdd(&g_ea[2 * dst + 1], ea[2 * e + 1]);
}

__global__ void k_eamean() {
    int i = blockIdx.x * 256 + threadIdx.x;
    if (i >= N_NODES) return;
    float d = fmaxf(g_deg[i], 1.f);
    g_ea[2 * i]     /= d;
    g_ea[2 * i + 1] /= d;
}

/* ------------------------------------------------------------------ */
/* SGEMM: C[M,N] = A[M,K] * B (+bias), double-buffered smem           */
/* EPI 0: +bias   1: gelu(+bias)   2: +bias + addsrc (residual)       */
/* ------------------------------------------------------------------ */
template<bool TRANSB, int EPI>
__global__ void __launch_bounds__(256) gemm_k(
        const float* __restrict__ A, const float* __restrict__ B,
        const float* __restrict__ bias, const float* __restrict__ addsrc,
        float* __restrict__ C, int M, int Ncols, int K)
{
    __shared__ float As[2][8][128];
    __shared__ float Bs[2][8][128];
    const int t   = threadIdx.x;
    const int tx  = t & 15, ty = t >> 4;
    const int row0 = blockIdx.y * 128, col0 = blockIdx.x * 128;
    const int la_r = t >> 1, la_k = (t & 1) * 4;    /* A / B^T loads  */
    const int lb_k = t >> 5, lb_n = (t & 31) * 4;   /* B normal loads */

    float acc[8][8];
    #pragma unroll
    for (int i = 0; i < 8; i++)
        #pragma unroll
        for (int j = 0; j < 8; j++) acc[i][j] = 0.f;

    /* prologue: load k-tile 0 into buffer 0 */
    {
        float4 av = *(const float4*)(A + (size_t)(row0 + la_r) * K + la_k);
        float4 bv;
        if (TRANSB) bv = *(const float4*)(B + (size_t)(col0 + la_r) * K + la_k);
        else        bv = *(const float4*)(B + (size_t)lb_k * Ncols + col0 + lb_n);
        As[0][la_k + 0][la_r] = av.x; As[0][la_k + 1][la_r] = av.y;
        As[0][la_k + 2][la_r] = av.z; As[0][la_k + 3][la_r] = av.w;
        if (TRANSB) {
            Bs[0][la_k + 0][la_r] = bv.x; Bs[0][la_k + 1][la_r] = bv.y;
            Bs[0][la_k + 2][la_r] = bv.z; Bs[0][la_k + 3][la_r] = bv.w;
        } else {
            *(float4*)&Bs[0][lb_k][lb_n] = bv;
        }
    }
    __syncthreads();

    for (int k0 = 0; k0 < K; k0 += 8) {
        const int cur = (k0 >> 3) & 1;
        const bool has_next = (k0 + 8 < K);
        float4 av, bv;
        if (has_next) {        /* issue next tile's global loads early */
            int kn = k0 + 8;
            av = *(const float4*)(A + (size_t)(row0 + la_r) * K + kn + la_k);
            if (TRANSB) bv = *(const float4*)(B + (size_t)(col0 + la_r) * K + kn + la_k);
            else        bv = *(const float4*)(B + (size_t)(kn + lb_k) * Ncols + col0 + lb_n);
        }
        #pragma unroll
        for (int kk = 0; kk < 8; kk++) {
            float4 a0 = *(const float4*)&As[cur][kk][ty * 4];
            float4 a1 = *(const float4*)&As[cur][kk][64 + ty * 4];
            float4 b0 = *(const float4*)&Bs[cur][kk][tx * 4];
            float4 b1 = *(const float4*)&Bs[cur][kk][64 + tx * 4];
            float a[8] = {a0.x,a0.y,a0.z,a0.w,a1.x,a1.y,a1.z,a1.w};
            float b[8] = {b0.x,b0.y,b0.z,b0.w,b1.x,b1.y,b1.z,b1.w};
            #pragma unroll
            for (int i = 0; i < 8; i++)
                #pragma unroll
                for (int j = 0; j < 8; j++)
                    acc[i][j] = fmaf(a[i], b[j], acc[i][j]);
        }
        if (has_next) {        /* write into the other buffer */
            const int nxt = cur ^ 1;
            As[nxt][la_k + 0][la_r] = av.x; As[nxt][la_k + 1][la_r] = av.y;
            As[nxt][la_k + 2][la_r] = av.z; As[nxt][la_k + 3][la_r] = av.w;
            if (TRANSB) {
                Bs[nxt][la_k + 0][la_r] = bv.x; Bs[nxt][la_k + 1][la_r] = bv.y;
                Bs[nxt][la_k + 2][la_r] = bv.z; Bs[nxt][la_k + 3][la_r] = bv.w;
            } else {
                *(float4*)&Bs[nxt][lb_k][lb_n] = bv;
            }
        }
        __syncthreads();
    }

    #pragma unroll
    for (int i = 0; i < 8; i++) {
        int rr = row0 + ((i < 4) ? ty * 4 + i : 64 + ty * 4 + i - 4);
        #pragma unroll
        for (int j = 0; j < 8; j++) {
            int cc = col0 + ((j < 4) ? tx * 4 + j : 64 + tx * 4 + j - 4);
            float v = acc[i][j] + bias[cc];
            if (EPI == 1) v = 0.5f * v * (1.f + erff(v * 0.7071067811865475f));
            if (EPI == 2) v += addsrc[(size_t)rr * Ncols + cc];
            C[(size_t)rr * Ncols + cc] = v;
        }
    }
}

/* ------------------------------------------------------------------ */
/* GATv2 edge scoring: one warp per edge (incl. self loops)           */
/* ------------------------------------------------------------------ */
__global__ void __launch_bounds__(256) k_score(
        const int* __restrict__ ei, const float* __restrict__ ea,
        const float* __restrict__ We, const float* __restrict__ att)
{
    int gw = (blockIdx.x * 256 + threadIdx.x) >> 5;
    int lane = threadIdx.x & 31;
    if (gw >= E2) return;
    int src, dst; float ea0, ea1;
    if (gw < NE) { src = ei[gw]; dst = ei[NE + gw]; ea0 = ea[2 * gw]; ea1 = ea[2 * gw + 1]; }
    else         { src = dst = gw - NE; ea0 = g_ea[2 * src]; ea1 = g_ea[2 * src + 1]; }
    const float* xlr = g_xl + (size_t)src * HID;
    const float* xrr = g_xr + (size_t)dst * HID;
    #pragma unroll
    for (int h = 0; h < NH; h++) {
        int j = h * 32 + lane;
        float v = xlr[j] + xrr[j] + ea0 * We[j] + ea1 * We[HID + j];
        v = v > 0.f ? v : 0.2f * v;                 /* leaky_relu slope 0.2 */
        float p = warp_sum(v * att[j]);
        if (lane == 0) {
            g_score[(size_t)gw * NH + h] = p;
            atomicMax(&g_smax[dst * NH + h], fenc(p));
        }
    }
}

__global__ void k_expsum(const int* __restrict__ ei) {
    int idx = blockIdx.x * 256 + threadIdx.x;       /* grid covers E2*NH */
    int e = idx >> 3, h = idx & 7;
    int dst = (e < NE) ? ei[NE + e] : (e - NE);
    float ex = expf(g_score[idx] - fdec(g_smax[dst * NH + h]));
    g_score[idx] = ex;
    atomicAdd(&g_ssum[dst * NH + h], ex);
}

/* weighted aggregation: warp per edge, vector RED into g_gat */
__global__ void __launch_bounds__(256) k_agg(const int* __restrict__ ei) {
    int gw = (blockIdx.x * 256 + threadIdx.x) >> 5;
    int lane = threadIdx.x & 31;
    if (gw >= E2) return;
    int src, dst;
    if (gw < NE) { src = ei[gw]; dst = ei[NE + gw]; }
    else         { src = dst = gw - NE; }
    float al = 0.f;
    if (lane < NH) al = g_score[(size_t)gw * NH + lane] / g_ssum[dst * NH + lane];
    const float* xlr = g_xl + (size_t)src * HID;
    float* orow = g_gat + (size_t)dst * HID;
    #pragma unroll
    for (int half = 0; half < 2; half++) {
        int j = half * 128 + lane * 4;
        float a = __shfl_sync(0xffffffffu, al, half * 4 + (lane >> 3));
        float4 xv = *(const float4*)(xlr + j);
        red_add_v4(orow + j, a * xv.x, a * xv.y, a * xv.z, a * xv.w);
    }
}

/* ------------------------------------------------------------------ */
/* LayerNorm over HID=256: one warp per row (optional pre-bias)       */
/* ------------------------------------------------------------------ */
__global__ void __launch_bounds__(256) k_ln(
        const float* __restrict__ in, const float* __restrict__ prebias,
        const float* __restrict__ gamma, const float* __restrict__ beta,
        float* __restrict__ out)
{
    int r = (blockIdx.x * 256 + threadIdx.x) >> 5;
    int lane = threadIdx.x & 31;
    if (r >= N_NODES) return;
    const float* row = in + (size_t)r * HID;
    float v[8], s = 0.f, sq = 0.f;
    #pragma unroll
    for (int t = 0; t < 8; t++) {
        int j = t * 32 + lane;
        v[t] = row[j] + (prebias ? prebias[j] : 0.f);
        s += v[t]; sq += v[t] * v[t];
    }
    s = warp_sum(s); sq = warp_sum(sq);
    float mean = s * (1.f / HID);
    float var  = sq * (1.f / HID) - mean * mean;
    float rs = rsqrtf(var + 1e-5f);
    #pragma unroll
    for (int t = 0; t < 8; t++) {
        int j = t * 32 + lane;
        out[(size_t)r * HID + j] = (v[t] - mean) * rs * gamma[j] + beta[j];
    }
}

/* ------------------------------------------------------------------ */
/* per-(graph,head) attention: 512 blocks, 256 threads                */
/* smem: Ks[32][516] + Vt[32][516] + Ps[8][512]                       */
/* ------------------------------------------------------------------ */
#define KS_STRIDE 516
#define ATT_SMEM_FLOATS (2 * 32 * KS_STRIDE + 8 * NPG)
#define ATT_SMEM_BYTES  (ATT_SMEM_FLOATS * 4)

__global__ void __launch_bounds__(256) k_attn(const float* __restrict__ qkv,
                                              float* __restrict__ out)
{
    extern __shared__ float sm[];
    float* Ks = sm;
    float* Vt = sm + 32 * KS_STRIDE;
    float* Ps = sm + 2 * 32 * KS_STRIDE;
    int g = blockIdx.x >> 3, h = blockIdx.x & 7;
    int t = threadIdx.x;
    const float* base = qkv + (size_t)g * NPG * (3 * HID);
    for (int idx = t; idx < NPG * HC; idx += 256) {
        int j = idx >> 5, c = idx & 31;
        Ks[c * KS_STRIDE + j] = base[j * (3 * HID) + HID     + h * HC + c];
        Vt[c * KS_STRIDE + j] = base[j * (3 * HID) + 2 * HID + h * HC + c];
    }
    __syncthreads();
    int w = t >> 5, lane = t & 31;
    float* pbuf = Ps + w * NPG;
    for (int r = w; r < NPG; r += 8) {
        float qv = base[r * (3 * HID) + h * HC + lane];
        float s[16];
        #pragma unroll
        for (int i = 0; i < 16; i++) s[i] = 0.f;
        #pragma unroll
        for (int c = 0; c < HC; c++) {
            float qc = __shfl_sync(0xffffffffu, qv, c);
            const float* krow = Ks + c * KS_STRIDE + lane * 4;
            #pragma unroll
            for (int gb = 0; gb < 4; gb++) {
                float4 k4 = *(const float4*)(krow + gb * 128);
                s[gb*4+0] = fmaf(qc, k4.x, s[gb*4+0]);
                s[gb*4+1] = fmaf(qc, k4.y, s[gb*4+1]);
                s[gb*4+2] = fmaf(qc, k4.z, s[gb*4+2]);
                s[gb*4+3] = fmaf(qc, k4.w, s[gb*4+3]);
            }
        }
        float m = -1e30f;
        #pragma unroll
        for (int i = 0; i < 16; i++) { s[i] *= 0.17677669529663688f; m = fmaxf(m, s[i]); }
        #pragma unroll
        for (int o = 16; o; o >>= 1) m = fmaxf(m, __shfl_xor_sync(0xffffffffu, m, o));
        float sum = 0.f;
        #pragma unroll
        for (int i = 0; i < 16; i++) { s[i] = expf(s[i] - m); sum += s[i]; }
        sum = warp_sum(sum);
        float inv = 1.f / sum;
        #pragma unroll
        for (int gb = 0; gb < 4; gb++) {
            float4 p4 = make_float4(s[gb*4]*inv, s[gb*4+1]*inv, s[gb*4+2]*inv, s[gb*4+3]*inv);
            *(float4*)(pbuf + gb * 128 + lane * 4) = p4;
        }
        __syncwarp();
        float o = 0.f;
        const float* vrow = Vt + lane * KS_STRIDE;
        #pragma unroll 4
        for (int j4 = 0; j4 < NPG / 4; j4++) {
            float4 p4 = *(const float4*)(pbuf + j4 * 4);
            float4 v4 = *(const float4*)(vrow + j4 * 4);
            o = fmaf(p4.x, v4.x, o); o = fmaf(p4.y, v4.y, o);
            o = fmaf(p4.z, v4.z, o); o = fmaf(p4.w, v4.w, o);
        }
        out[((size_t)g * NPG + r) * HID + h * HC + lane] = o;
        __syncwarp();
    }
}

/* combined = sigmoid(alpha)*local + (1-sigmoid(alpha))*global */
__global__ void k_combine(const float* __restrict__ alpha) {
    int i = blockIdx.x * 256 + threadIdx.x;          /* grid covers N*HID */
    float a = 1.f / (1.f + expf(-alpha[0]));
    g_comb[i] = a * g_local[i] + (1.f - a) * g_glob[i];
}

/* ------------------------------------------------------------------ */
extern "C" void kernel_launch(void* const* d_in, const int* in_sizes, int n_in,
                              void* d_out, int out_size)
{
    const float* x        = (const float*)d_in[0];
    const float* edge_at  = (const float*)d_in[1];
    const float* W_l      = (const float*)d_in[2];
    const float* b_l      = (const float*)d_in[3];
    const float* W_r      = (const float*)d_in[4];
    const float* b_r      = (const float*)d_in[5];
    const float* W_e      = (const float*)d_in[6];
    const float* att      = (const float*)d_in[7];
    const float* bias_gat = (const float*)d_in[8];
    const float* in_w     = (const float*)d_in[9];
    const float* in_b     = (const float*)d_in[10];
    const float* out_w    = (const float*)d_in[11];
    const float* out_b    = (const float*)d_in[12];
    const float* alpha    = (const float*)d_in[13];
    const float* W1       = (const float*)d_in[14];
    const float* b1       = (const float*)d_in[15];
    const float* W2       = (const float*)d_in[16];
    const float* b2       = (const float*)d_in[17];
    const float* g1       = (const float*)d_in[18];
    const float* be1      = (const float*)d_in[19];
    const float* g2       = (const float*)d_in[20];
    const float* be2      = (const float*)d_in[21];
    const float* g3       = (const float*)d_in[22];
    const float* be3      = (const float*)d_in[23];
    const int*   ei       = (const int*)d_in[24];
    float*       out      = (float*)d_out;

    float *p_xl, *p_xr, *p_gat, *p_local, *p_attn, *p_glob, *p_comb, *p_qkv, *p_mid;
    cudaGetSymbolAddress((void**)&p_xl,    g_xl);
    cudaGetSymbolAddress((void**)&p_xr,    g_xr);
    cudaGetSymbolAddress((void**)&p_gat,   g_gat);
    cudaGetSymbolAddress((void**)&p_local, g_local);
    cudaGetSymbolAddress((void**)&p_attn,  g_attn);
    cudaGetSymbolAddress((void**)&p_glob,  g_glob);
    cudaGetSymbolAddress((void**)&p_comb,  g_comb);
    cudaGetSymbolAddress((void**)&p_qkv,   g_qkv);
    cudaGetSymbolAddress((void**)&p_mid,   g_mid);

    cudaFuncSetAttribute(k_attn, cudaFuncAttributeMaxDynamicSharedMemorySize,
                         ATT_SMEM_BYTES);

    /* ---- GATv2 branch ---- */
    k_init   <<<N_NODES * HID / 256, 256>>>();
    k_deg    <<<NE / 256, 256>>>(ei, edge_at);
    k_eamean <<<N_NODES / 256, 256>>>();
    gemm_k<false,0><<<dim3(HID/128, N_NODES/128), 256>>>(x, W_l, b_l, nullptr, p_xl, N_NODES, HID, HID);
    gemm_k<false,0><<<dim3(HID/128, N_NODES/128), 256>>>(x, W_r, b_r, nullptr, p_xr, N_NODES, HID, HID);
    k_score  <<<E2 / 8, 256>>>(ei, edge_at, W_e, att);
    k_expsum <<<E2 * NH / 256, 256>>>(ei);
    k_agg    <<<E2 / 8, 256>>>(ei);
    k_ln     <<<N_NODES / 8, 256>>>(p_gat, bias_gat, g1, be1, p_local);

    /* ---- global attention branch ---- */
    gemm_k<true,0><<<dim3(768/128, N_NODES/128), 256>>>(x, in_w, in_b, nullptr, p_qkv, N_NODES, 3*HID, HID);
    k_attn   <<<NG * NH, 256, ATT_SMEM_BYTES>>>(p_qkv, p_attn);
    gemm_k<true,0><<<dim3(HID/128, N_NODES/128), 256>>>(p_attn, out_w, out_b, nullptr, p_glob, N_NODES, HID, HID);
    k_ln     <<<N_NODES / 8, 256>>>(p_glob, nullptr, g2, be2, p_glob);

    /* ---- combine + FFN + final LN ---- */
    k_combine<<<N_NODES * HID / 256, 256>>>(alpha);
    gemm_k<false,1><<<dim3(1024/128, N_NODES/128), 256>>>(p_comb, W1, b1, nullptr, p_mid, N_NODES, 4*HID, HID);
    gemm_k<false,2><<<dim3(HID/128, N_NODES/128), 256>>>(p_mid, W2, b2, p_comb, p_glob, N_NODES, HID, 4*HID);
    k_ln     <<<N_NODES / 8, 256>>>(p_glob, nullptr, g3, be3, out);
}

// round 10
// speedup vs baseline: 1.1948x; 1.1948x over previous
#include <cuda_runtime.h>
#include <cuda_bf16.h>
#include <math.h>

#define N_NODES 32768
#define HID     256
#define NE      524288
#define NH      8
#define HC      32
#define NG      64
#define NPG     512
#define E2      (NE + N_NODES)   /* 557056 edges incl. self loops */

/* ------------------------------------------------------------------ */
/* scratch (device globals; no runtime allocation allowed)            */
/* ------------------------------------------------------------------ */
__device__ __align__(128) float    g_xl   [N_NODES * HID];
__device__ __align__(128) float    g_xr   [N_NODES * HID];
__device__ __align__(128) float    g_gat  [N_NODES * HID];
__device__ __align__(128) float    g_local[N_NODES * HID];
__device__ __align__(128) float    g_attn [N_NODES * HID];
__device__ __align__(128) float    g_glob [N_NODES * HID];
__device__ __align__(128) float    g_comb [N_NODES * HID];
__device__ __align__(128) float    g_qkv  [N_NODES * 3 * HID];
__device__ __align__(128) float    g_mid  [N_NODES * 4 * HID];
__device__ __align__(128) float    g_score[E2 * NH];          /* scores, then exp */
__device__ __align__(128) unsigned g_smax [N_NODES * NH];
__device__ __align__(128) float    g_ssum [N_NODES * NH];
__device__ __align__(128) float    g_deg  [N_NODES];
__device__ __align__(128) float    g_ea   [N_NODES * 2];      /* sum -> mean */

/* ------------------------------------------------------------------ */
/* helpers                                                            */
/* ------------------------------------------------------------------ */
__device__ __forceinline__ unsigned fenc(float f) {
    unsigned u = __float_as_uint(f);
    return (u & 0x80000000u) ? ~u : (u | 0x80000000u);
}
__device__ __forceinline__ float fdec(unsigned u) {
    return (u & 0x80000000u) ? __uint_as_float(u & 0x7fffffffu)
                             : __uint_as_float(~u);
}
__device__ __forceinline__ float warp_sum(float v) {
    #pragma unroll
    for (int o = 16; o; o >>= 1) v += __shfl_xor_sync(0xffffffffu, v, o);
    return v;
}
__device__ __forceinline__ void red_add_v4(float* p, float a, float b, float c, float d) {
    asm volatile("red.global.add.v4.f32 [%0], {%1,%2,%3,%4};"
                 :: "l"(p), "f"(a), "f"(b), "f"(c), "f"(d) : "memory");
}
__device__ __forceinline__ unsigned f2tf32(float f) {
    unsigned u;
    asm("cvt.rna.tf32.f32 %0, %1;" : "=r"(u) : "f"(f));
    return u;
}
#define MMA_TF32(c, a, b) \
    asm volatile("mma.sync.aligned.m16n8k8.row.col.f32.tf32.tf32.f32 " \
        "{%0,%1,%2,%3}, {%4,%5,%6,%7}, {%8,%9}, {%0,%1,%2,%3};" \
        : "+f"((c)[0]), "+f"((c)[1]), "+f"((c)[2]), "+f"((c)[3]) \
        : "r"((a)[0]), "r"((a)[1]), "r"((a)[2]), "r"((a)[3]), \
          "r"((b)[0]), "r"((b)[1]))

/* ------------------------------------------------------------------ */
/* init: zero all accumulators                                        */
/* ------------------------------------------------------------------ */
__global__ void k_init() {
    int i = blockIdx.x * 256 + threadIdx.x;          /* grid covers N*HID */
    g_gat[i] = 0.f;
    if (i < N_NODES)       g_deg[i]  = 0.f;
    if (i < N_NODES * 2)   g_ea[i]   = 0.f;
    if (i < N_NODES * NH) { g_smax[i] = 0u; g_ssum[i] = 0.f; }
}

/* degree + edge-attr sums over incoming edges */
__global__ void k_deg(const int* __restrict__ ei, const float* __restrict__ ea) {
    int e = blockIdx.x * 256 + threadIdx.x;
    if (e >= NE) return;
    int dst = ei[NE + e];
    atomicAdd(&g_deg[dst], 1.f);
    atomicAdd(&g_ea[2 * dst],     ea[2 * e]);
    atomicAdd(&g_ea[2 * dst + 1], ea[2 * e + 1]);
}

__global__ void k_eamean() {
    int i = blockIdx.x * 256 + threadIdx.x;
    if (i >= N_NODES) return;
    float d = fmaxf(g_deg[i], 1.f);
    g_ea[2 * i]     /= d;
    g_ea[2 * i + 1] /= d;
}

/* ------------------------------------------------------------------ */
/* tf32 tensor-core GEMM: C[M,N] = A[M,K]*B (+bias) with epilogues    */
/* block tile 128x128, K-chunk 32, double-buffered dynamic smem       */
/* As stride 36 (banks 4r+c distinct), Bs stride 136 (8k+n distinct)  */
/* EPI 0: +bias   1: gelu(+bias)   2: +bias + addsrc (residual)       */
/* ------------------------------------------------------------------ */
#define AS_STRIDE 36
#define BS_STRIDE 136
#define AS_BUF (128 * AS_STRIDE)
#define BS_BUF (32 * BS_STRIDE)
#define TC_SMEM ((2 * AS_BUF + 2 * BS_BUF) * 4)   /* 71680 bytes */

template<bool TRANSB, int EPI>
__global__ void __launch_bounds__(256) gemm_tc(
        const float* __restrict__ A, const float* __restrict__ B,
        const float* __restrict__ bias, const float* __restrict__ addsrc,
        float* __restrict__ C, int M, int Ncols, int K)
{
    extern __shared__ unsigned char sdyn[];
    unsigned* As = (unsigned*)sdyn;           /* [2][128][36] */
    unsigned* Bs = As + 2 * AS_BUF;           /* [2][32][136] */
    const int t    = threadIdx.x;
    const int lane = t & 31, w = t >> 5;
    const int wm = w & 1, wn = w >> 1;        /* warp tile: 64(M) x 32(N) */
    const int grp = lane >> 2, qd = lane & 3;
    const int row0 = blockIdx.y * 128, col0 = blockIdx.x * 128;

    float c[4][4][4];
    #pragma unroll
    for (int i = 0; i < 4; i++)
        #pragma unroll
        for (int j = 0; j < 4; j++) {
            c[i][j][0] = 0.f; c[i][j][1] = 0.f;
            c[i][j][2] = 0.f; c[i][j][3] = 0.f;
        }

    float4 sa[4], sb[4];

    /* ---- global -> reg staging ---- */
    auto load_chunk = [&](int k0) {
        #pragma unroll
        for (int i = 0; i < 4; i++) {
            int idx = t * 4 + i;
            sa[i] = *(const float4*)(A + (size_t)(row0 + (idx >> 3)) * K + k0 + (idx & 7) * 4);
            if (TRANSB)
                sb[i] = *(const float4*)(B + (size_t)(col0 + (idx >> 3)) * K + k0 + (idx & 7) * 4);
            else
                sb[i] = *(const float4*)(B + (size_t)(k0 + (idx >> 5)) * Ncols + col0 + (idx & 31) * 4);
        }
    };
    /* ---- reg -> smem (with fp32 -> tf32 conversion) ---- */
    auto store_chunk = [&](int buf) {
        unsigned* Ab = As + buf * AS_BUF;
        unsigned* Bb = Bs + buf * BS_BUF;
        #pragma unroll
        for (int i = 0; i < 4; i++) {
            int idx = t * 4 + i;
            uint4 ua = make_uint4(f2tf32(sa[i].x), f2tf32(sa[i].y),
                                  f2tf32(sa[i].z), f2tf32(sa[i].w));
            *(uint4*)&Ab[(idx >> 3) * AS_STRIDE + (idx & 7) * 4] = ua;
            if (TRANSB) {
                int n = idx >> 3, kb = (idx & 7) * 4;
                Bb[(kb + 0) * BS_STRIDE + n] = f2tf32(sb[i].x);
                Bb[(kb + 1) * BS_STRIDE + n] = f2tf32(sb[i].y);
                Bb[(kb + 2) * BS_STRIDE + n] = f2tf32(sb[i].z);
                Bb[(kb + 3) * BS_STRIDE + n] = f2tf32(sb[i].w);
            } else {
                uint4 ub = make_uint4(f2tf32(sb[i].x), f2tf32(sb[i].y),
                                      f2tf32(sb[i].z), f2tf32(sb[i].w));
                *(uint4*)&Bb[(idx >> 5) * BS_STRIDE + (idx & 31) * 4] = ub;
            }
        }
    };

    load_chunk(0);
    store_chunk(0);
    __syncthreads();

    const int nchunks = K >> 5;
    for (int ch = 0; ch < nchunks; ch++) {
        const int cur = ch & 1;
        const bool more = (ch + 1 < nchunks);
        if (more) load_chunk((ch + 1) * 32);

        const unsigned* Ab = As + cur * AS_BUF + (wm * 64) * AS_STRIDE;
        const unsigned* Bb = Bs + cur * BS_BUF + wn * 32;
        #pragma unroll
        for (int kk = 0; kk < 4; kk++) {
            unsigned a[4][4], b[4][2];
            #pragma unroll
            for (int mt = 0; mt < 4; mt++) {
                const unsigned* ap = Ab + (mt * 16 + grp) * AS_STRIDE + kk * 8 + qd;
                a[mt][0] = ap[0];
                a[mt][1] = ap[8 * AS_STRIDE];
                a[mt][2] = ap[4];
                a[mt][3] = ap[8 * AS_STRIDE + 4];
            }
            #pragma unroll
            for (int nt = 0; nt < 4; nt++) {
                const unsigned* bp = Bb + (kk * 8 + qd) * BS_STRIDE + nt * 8 + grp;
                b[nt][0] = bp[0];
                b[nt][1] = bp[4 * BS_STRIDE];
            }
            #pragma unroll
            for (int mt = 0; mt < 4; mt++)
                #pragma unroll
                for (int nt = 0; nt < 4; nt++)
                    MMA_TF32(c[mt][nt], a[mt], b[nt]);
        }
        if (more) store_chunk((ch + 1) & 1);
        __syncthreads();
    }

    /* ---- epilogue ---- */
    #pragma unroll
    for (int mt = 0; mt < 4; mt++) {
        #pragma unroll
        for (int half = 0; half < 2; half++) {
            int rr = row0 + wm * 64 + mt * 16 + grp + half * 8;
            #pragma unroll
            for (int nt = 0; nt < 4; nt++) {
                int cc = col0 + wn * 32 + nt * 8 + qd * 2;
                float v0 = c[mt][nt][half * 2 + 0] + bias[cc];
                float v1 = c[mt][nt][half * 2 + 1] + bias[cc + 1];
                if (EPI == 1) {
                    v0 = 0.5f * v0 * (1.f + erff(v0 * 0.7071067811865475f));
                    v1 = 0.5f * v1 * (1.f + erff(v1 * 0.7071067811865475f));
                }
                if (EPI == 2) {
                    const float* ar = addsrc + (size_t)rr * Ncols + cc;
                    v0 += ar[0]; v1 += ar[1];
                }
                float2 o = make_float2(v0, v1);
                *(float2*)&C[(size_t)rr * Ncols + cc] = o;
            }
        }
    }
}

/* ------------------------------------------------------------------ */
/* GATv2 edge scoring: one warp per edge (incl. self loops)           */
/* ------------------------------------------------------------------ */
__global__ void __launch_bounds__(256) k_score(
        const int* __restrict__ ei, const float* __restrict__ ea,
        const float* __restrict__ We, const float* __restrict__ att)
{
    int gw = (blockIdx.x * 256 + threadIdx.x) >> 5;
    int lane = threadIdx.x & 31;
    if (gw >= E2) return;
    int src, dst; float ea0, ea1;
    if (gw < NE) { src = ei[gw]; dst = ei[NE + gw]; ea0 = ea[2 * gw]; ea1 = ea[2 * gw + 1]; }
    else         { src = dst = gw - NE; ea0 = g_ea[2 * src]; ea1 = g_ea[2 * src + 1]; }
    const float* xlr = g_xl + (size_t)src * HID;
    const float* xrr = g_xr + (size_t)dst * HID;
    #pragma unroll
    for (int h = 0; h < NH; h++) {
        int j = h * 32 + lane;
        float v = xlr[j] + xrr[j] + ea0 * We[j] + ea1 * We[HID + j];
        v = v > 0.f ? v : 0.2f * v;                 /* leaky_relu slope 0.2 */
        float p = warp_sum(v * att[j]);
        if (lane == 0) {
            g_score[(size_t)gw * NH + h] = p;
            atomicMax(&g_smax[dst * NH + h], fenc(p));
        }
    }
}

__global__ void k_expsum(const int* __restrict__ ei) {
    int idx = blockIdx.x * 256 + threadIdx.x;       /* grid covers E2*NH */
    int e = idx >> 3, h = idx & 7;
    int dst = (e < NE) ? ei[NE + e] : (e - NE);
    float ex = expf(g_score[idx] - fdec(g_smax[dst * NH + h]));
    g_score[idx] = ex;
    atomicAdd(&g_ssum[dst * NH + h], ex);
}

/* weighted aggregation: warp per edge, vector RED into g_gat */
__global__ void __launch_bounds__(256) k_agg(const int* __restrict__ ei) {
    int gw = (blockIdx.x * 256 + threadIdx.x) >> 5;
    int lane = threadIdx.x & 31;
    if (gw >= E2) return;
    int src, dst;
    if (gw < NE) { src = ei[gw]; dst = ei[NE + gw]; }
    else         { src = dst = gw - NE; }
    float al = 0.f;
    if (lane < NH) al = g_score[(size_t)gw * NH + lane] / g_ssum[dst * NH + lane];
    const float* xlr = g_xl + (size_t)src * HID;
    float* orow = g_gat + (size_t)dst * HID;
    #pragma unroll
    for (int half = 0; half < 2; half++) {
        int j = half * 128 + lane * 4;
        float a = __shfl_sync(0xffffffffu, al, half * 4 + (lane >> 3));
        float4 xv = *(const float4*)(xlr + j);
        red_add_v4(orow + j, a * xv.x, a * xv.y, a * xv.z, a * xv.w);
    }
}

/* ------------------------------------------------------------------ */
/* LayerNorm over HID=256: one warp per row (optional pre-bias)       */
/* ------------------------------------------------------------------ */
__global__ void __launch_bounds__(256) k_ln(
        const float* __restrict__ in, const float* __restrict__ prebias,
        const float* __restrict__ gamma, const float* __restrict__ beta,
        float* __restrict__ out)
{
    int r = (blockIdx.x * 256 + threadIdx.x) >> 5;
    int lane = threadIdx.x & 31;
    if (r >= N_NODES) return;
    const float* row = in + (size_t)r * HID;
    float v[8], s = 0.f, sq = 0.f;
    #pragma unroll
    for (int t = 0; t < 8; t++) {
        int j = t * 32 + lane;
        v[t] = row[j] + (prebias ? prebias[j] : 0.f);
        s += v[t]; sq += v[t] * v[t];
    }
    s = warp_sum(s); sq = warp_sum(sq);
    float mean = s * (1.f / HID);
    float var  = sq * (1.f / HID) - mean * mean;
    float rs = rsqrtf(var + 1e-5f);
    #pragma unroll
    for (int t = 0; t < 8; t++) {
        int j = t * 32 + lane;
        out[(size_t)r * HID + j] = (v[t] - mean) * rs * gamma[j] + beta[j];
    }
}

/* ------------------------------------------------------------------ */
/* per-(graph,head) attention: 512 blocks, 256 threads                */
/* smem: Ks[32][516] + Vt[32][516] + Ps[8][512]                       */
/* ------------------------------------------------------------------ */
#define KS_STRIDE 516
#define ATT_SMEM_FLOATS (2 * 32 * KS_STRIDE + 8 * NPG)
#define ATT_SMEM_BYTES  (ATT_SMEM_FLOATS * 4)

__global__ void __launch_bounds__(256) k_attn(const float* __restrict__ qkv,
                                              float* __restrict__ out)
{
    extern __shared__ unsigned char sdyn[];
    float* sm = (float*)sdyn;
    float* Ks = sm;
    float* Vt = sm + 32 * KS_STRIDE;
    float* Ps = sm + 2 * 32 * KS_STRIDE;
    int g = blockIdx.x >> 3, h = blockIdx.x & 7;
    int t = threadIdx.x;
    const float* base = qkv + (size_t)g * NPG * (3 * HID);
    for (int idx = t; idx < NPG * HC; idx += 256) {
        int j = idx >> 5, c = idx & 31;
        Ks[c * KS_STRIDE + j] = base[j * (3 * HID) + HID     + h * HC + c];
        Vt[c * KS_STRIDE + j] = base[j * (3 * HID) + 2 * HID + h * HC + c];
    }
    __syncthreads();
    int w = t >> 5, lane = t & 31;
    float* pbuf = Ps + w * NPG;
    for (int r = w; r < NPG; r += 8) {
        float qv = base[r * (3 * HID) + h * HC + lane];
        float s[16];
        #pragma unroll
        for (int i = 0; i < 16; i++) s[i] = 0.f;
        #pragma unroll
        for (int c = 0; c < HC; c++) {
            float qc = __shfl_sync(0xffffffffu, qv, c);
            const float* krow = Ks + c * KS_STRIDE + lane * 4;
            #pragma unroll
            for (int gb = 0; gb < 4; gb++) {
                float4 k4 = *(const float4*)(krow + gb * 128);
                s[gb*4+0] = fmaf(qc, k4.x, s[gb*4+0]);
                s[gb*4+1] = fmaf(qc, k4.y, s[gb*4+1]);
                s[gb*4+2] = fmaf(qc, k4.z, s[gb*4+2]);
                s[gb*4+3] = fmaf(qc, k4.w, s[gb*4+3]);
            }
        }
        float m = -1e30f;
        #pragma unroll
        for (int i = 0; i < 16; i++) { s[i] *= 0.17677669529663688f; m = fmaxf(m, s[i]); }
        #pragma unroll
        for (int o = 16; o; o >>= 1) m = fmaxf(m, __shfl_xor_sync(0xffffffffu, m, o));
        float sum = 0.f;
        #pragma unroll
        for (int i = 0; i < 16; i++) { s[i] = expf(s[i] - m); sum += s[i]; }
        sum = warp_sum(sum);
        float inv = 1.f / sum;
        #pragma unroll
        for (int gb = 0; gb < 4; gb++) {
            float4 p4 = make_float4(s[gb*4]*inv, s[gb*4+1]*inv, s[gb*4+2]*inv, s[gb*4+3]*inv);
            *(float4*)(pbuf + gb * 128 + lane * 4) = p4;
        }
        __syncwarp();
        float o = 0.f;
        const float* vrow = Vt + lane * KS_STRIDE;
        #pragma unroll 4
        for (int j4 = 0; j4 < NPG / 4; j4++) {
            float4 p4 = *(const float4*)(pbuf + j4 * 4);
            float4 v4 = *(const float4*)(vrow + j4 * 4);
            o = fmaf(p4.x, v4.x, o); o = fmaf(p4.y, v4.y, o);
            o = fmaf(p4.z, v4.z, o); o = fmaf(p4.w, v4.w, o);
        }
        out[((size_t)g * NPG + r) * HID + h * HC + lane] = o;
        __syncwarp();
    }
}

/* combined = sigmoid(alpha)*local + (1-sigmoid(alpha))*global */
__global__ void k_combine(const float* __restrict__ alpha) {
    int i = blockIdx.x * 256 + threadIdx.x;          /* grid covers N*HID */
    float a = 1.f / (1.f + expf(-alpha[0]));
    g_comb[i] = a * g_local[i] + (1.f - a) * g_glob[i];
}

/* ------------------------------------------------------------------ */
extern "C" void kernel_launch(void* const* d_in, const int* in_sizes, int n_in,
                              void* d_out, int out_size)
{
    const float* x        = (const float*)d_in[0];
    const float* edge_at  = (const float*)d_in[1];
    const float* W_l      = (const float*)d_in[2];
    const float* b_l      = (const float*)d_in[3];
    const float* W_r      = (const float*)d_in[4];
    const float* b_r      = (const float*)d_in[5];
    const float* W_e      = (const float*)d_in[6];
    const float* att      = (const float*)d_in[7];
    const float* bias_gat = (const float*)d_in[8];
    const float* in_w     = (const float*)d_in[9];
    const float* in_b     = (const float*)d_in[10];
    const float* out_w    = (const float*)d_in[11];
    const float* out_b    = (const float*)d_in[12];
    const float* alpha    = (const float*)d_in[13];
    const float* W1       = (const float*)d_in[14];
    const float* b1       = (const float*)d_in[15];
    const float* W2       = (const float*)d_in[16];
    const float* b2       = (const float*)d_in[17];
    const float* g1       = (const float*)d_in[18];
    const float* be1      = (const float*)d_in[19];
    const float* g2       = (const float*)d_in[20];
    const float* be2      = (const float*)d_in[21];
    const float* g3       = (const float*)d_in[22];
    const float* be3      = (const float*)d_in[23];
    const int*   ei       = (const int*)d_in[24];
    float*       out      = (float*)d_out;

    float *p_xl, *p_xr, *p_gat, *p_local, *p_attn, *p_glob, *p_comb, *p_qkv, *p_mid;
    cudaGetSymbolAddress((void**)&p_xl,    g_xl);
    cudaGetSymbolAddress((void**)&p_xr,    g_xr);
    cudaGetSymbolAddress((void**)&p_gat,   g_gat);
    cudaGetSymbolAddress((void**)&p_local, g_local);
    cudaGetSymbolAddress((void**)&p_attn,  g_attn);
    cudaGetSymbolAddress((void**)&p_glob,  g_glob);
    cudaGetSymbolAddress((void**)&p_comb,  g_comb);
    cudaGetSymbolAddress((void**)&p_qkv,   g_qkv);
    cudaGetSymbolAddress((void**)&p_mid,   g_mid);

    cudaFuncSetAttribute(k_attn, cudaFuncAttributeMaxDynamicSharedMemorySize,
                         ATT_SMEM_BYTES);
    cudaFuncSetAttribute(gemm_tc<false,0>, cudaFuncAttributeMaxDynamicSharedMemorySize, TC_SMEM);
    cudaFuncSetAttribute(gemm_tc<true, 0>, cudaFuncAttributeMaxDynamicSharedMemorySize, TC_SMEM);
    cudaFuncSetAttribute(gemm_tc<false,1>, cudaFuncAttributeMaxDynamicSharedMemorySize, TC_SMEM);
    cudaFuncSetAttribute(gemm_tc<false,2>, cudaFuncAttributeMaxDynamicSharedMemorySize, TC_SMEM);

    /* ---- GATv2 branch ---- */
    k_init   <<<N_NODES * HID / 256, 256>>>();
    k_deg    <<<NE / 256, 256>>>(ei, edge_at);
    k_eamean <<<N_NODES / 256, 256>>>();
    gemm_tc<false,0><<<dim3(HID/128, N_NODES/128), 256, TC_SMEM>>>(x, W_l, b_l, nullptr, p_xl, N_NODES, HID, HID);
    gemm_tc<false,0><<<dim3(HID/128, N_NODES/128), 256, TC_SMEM>>>(x, W_r, b_r, nullptr, p_xr, N_NODES, HID, HID);
    k_score  <<<E2 / 8, 256>>>(ei, edge_at, W_e, att);
    k_expsum <<<E2 * NH / 256, 256>>>(ei);
    k_agg    <<<E2 / 8, 256>>>(ei);
    k_ln     <<<N_NODES / 8, 256>>>(p_gat, bias_gat, g1, be1, p_local);

    /* ---- global attention branch ---- */
    gemm_tc<true,0><<<dim3(768/128, N_NODES/128), 256, TC_SMEM>>>(x, in_w, in_b, nullptr, p_qkv, N_NODES, 3*HID, HID);
    k_attn   <<<NG * NH, 256, ATT_SMEM_BYTES>>>(p_qkv, p_attn);
    gemm_tc<true,0><<<dim3(HID/128, N_NODES/128), 256, TC_SMEM>>>(p_attn, out_w, out_b, nullptr, p_glob, N_NODES, HID, HID);
    k_ln     <<<N_NODES / 8, 256>>>(p_glob, nullptr, g2, be2, p_glob);

    /* ---- combine + FFN + final LN ---- */
    k_combine<<<N_NODES * HID / 256, 256>>>(alpha);
    gemm_tc<false,1><<<dim3(1024/128, N_NODES/128), 256, TC_SMEM>>>(p_comb, W1, b1, nullptr, p_mid, N_NODES, 4*HID, HID);
    gemm_tc<false,2><<<dim3(HID/128, N_NODES/128), 256, TC_SMEM>>>(p_mid, W2, b2, p_comb, p_glob, N_NODES, HID, 4*HID);
    k_ln     <<<N_NODES / 8, 256>>>(p_glob, nullptr, g3, be3, out);
}